// round 5
// baseline (speedup 1.0000x reference)
#include <cuda_runtime.h>
#include <math.h>

#define B_   8
#define T_   2048
#define C_   1024
#define MTOT (B_ * T_)

// ---------------- scratch (device globals; no cudaMalloc allowed) ----------
__device__ float g_Q[(size_t)B_ * T_ * C_];   // 64 MB
__device__ float g_K[(size_t)B_ * T_ * C_];   // 64 MB
__device__ float g_V[(size_t)B_ * T_ * C_];   // 64 MB
__device__ float g_S[(size_t)B_ * T_ * T_];   // 128 MB  scores -> probabilities (in place)

// ============================================================================
// Register-tiled SGEMM bodies: 128x128 tile, BK=16, 256 threads, 8x8 per thread,
// double-buffered smem, single __syncthreads per k-tile.
// ============================================================================

// C[m,n] = alpha * sum_k A[m,k]*B[n,k]  (+ bias[n])          (NT: both K-contig)
__device__ __forceinline__ void gemm_nt_tile(
    const float* __restrict__ A, int lda,
    const float* __restrict__ B, int ldb,
    float* __restrict__ C, int ldc,
    const float* __restrict__ bias,
    int m0, int n0, int ktiles, float alpha)
{
    __shared__ __align__(16) float As[2][16][128];
    __shared__ __align__(16) float Bs[2][16][128];

    const int tid = threadIdx.x;
    const int tx  = tid & 15;        // column group (N)
    const int ty  = tid >> 4;        // row group (M)
    const int lm  = tid >> 2;        // 0..63 (row within tile, + 64 for 2nd load)
    const int lk  = (tid & 3) << 2;  // 0,4,8,12 (k offset)

    float acc[8][8];
#pragma unroll
    for (int i = 0; i < 8; i++)
#pragma unroll
        for (int j = 0; j < 8; j++) acc[i][j] = 0.f;

    float4 ra[2], rb[2];

    auto ldg = [&](int kt) {
#pragma unroll
        for (int i = 0; i < 2; i++) {
            ra[i] = *reinterpret_cast<const float4*>(A + (m0 + lm + i * 64) * lda + kt * 16 + lk);
            rb[i] = *reinterpret_cast<const float4*>(B + (n0 + lm + i * 64) * ldb + kt * 16 + lk);
        }
    };
    auto sts = [&](int buf) {
#pragma unroll
        for (int i = 0; i < 2; i++) {
            As[buf][lk + 0][lm + i * 64] = ra[i].x;
            As[buf][lk + 1][lm + i * 64] = ra[i].y;
            As[buf][lk + 2][lm + i * 64] = ra[i].z;
            As[buf][lk + 3][lm + i * 64] = ra[i].w;
            Bs[buf][lk + 0][lm + i * 64] = rb[i].x;
            Bs[buf][lk + 1][lm + i * 64] = rb[i].y;
            Bs[buf][lk + 2][lm + i * 64] = rb[i].z;
            Bs[buf][lk + 3][lm + i * 64] = rb[i].w;
        }
    };

    ldg(0); sts(0); __syncthreads();

    for (int kt = 0; kt < ktiles; kt++) {
        const int cur = kt & 1;
        if (kt + 1 < ktiles) ldg(kt + 1);
#pragma unroll
        for (int k = 0; k < 16; k++) {
            float4 a0 = *reinterpret_cast<const float4*>(&As[cur][k][ty * 8]);
            float4 a1 = *reinterpret_cast<const float4*>(&As[cur][k][ty * 8 + 4]);
            float4 b0 = *reinterpret_cast<const float4*>(&Bs[cur][k][tx * 8]);
            float4 b1 = *reinterpret_cast<const float4*>(&Bs[cur][k][tx * 8 + 4]);
            float av[8] = {a0.x, a0.y, a0.z, a0.w, a1.x, a1.y, a1.z, a1.w};
            float bv[8] = {b0.x, b0.y, b0.z, b0.w, b1.x, b1.y, b1.z, b1.w};
#pragma unroll
            for (int i = 0; i < 8; i++)
#pragma unroll
                for (int j = 0; j < 8; j++)
                    acc[i][j] = fmaf(av[i], bv[j], acc[i][j]);
        }
        if (kt + 1 < ktiles) { sts(cur ^ 1); __syncthreads(); }
    }

    float4 bb0 = {0.f, 0.f, 0.f, 0.f}, bb1 = {0.f, 0.f, 0.f, 0.f};
    if (bias) {
        bb0 = *reinterpret_cast<const float4*>(bias + n0 + tx * 8);
        bb1 = *reinterpret_cast<const float4*>(bias + n0 + tx * 8 + 4);
    }
#pragma unroll
    for (int i = 0; i < 8; i++) {
        const int m = m0 + ty * 8 + i;
        float4 o0, o1;
        o0.x = acc[i][0] * alpha + bb0.x;
        o0.y = acc[i][1] * alpha + bb0.y;
        o0.z = acc[i][2] * alpha + bb0.z;
        o0.w = acc[i][3] * alpha + bb0.w;
        o1.x = acc[i][4] * alpha + bb1.x;
        o1.y = acc[i][5] * alpha + bb1.y;
        o1.z = acc[i][6] * alpha + bb1.z;
        o1.w = acc[i][7] * alpha + bb1.w;
        *reinterpret_cast<float4*>(C + m * ldc + n0 + tx * 8)     = o0;
        *reinterpret_cast<float4*>(C + m * ldc + n0 + tx * 8 + 4) = o1;
    }
}

// C[m,n] = sum_k A[m,k]*B[k,n]            (NN: A K-contig, B N-contig)
__device__ __forceinline__ void gemm_nn_tile(
    const float* __restrict__ A, int lda,
    const float* __restrict__ B, int ldb,
    float* __restrict__ C, int ldc,
    int m0, int n0, int ktiles)
{
    __shared__ __align__(16) float As[2][16][128];
    __shared__ __align__(16) float Bs[2][16][128];

    const int tid = threadIdx.x;
    const int tx  = tid & 15;
    const int ty  = tid >> 4;
    const int lm  = tid >> 2;        // A loader: row 0..63 (+64)
    const int lk  = (tid & 3) << 2;  // A loader: k offset 0,4,8,12
    const int lbk = tid >> 5;        // B loader: k row 0..7 (+8)
    const int lbn = (tid & 31) << 2; // B loader: col 0..124

    float acc[8][8];
#pragma unroll
    for (int i = 0; i < 8; i++)
#pragma unroll
        for (int j = 0; j < 8; j++) acc[i][j] = 0.f;

    float4 ra[2], rb[2];

    auto ldg = [&](int kt) {
#pragma unroll
        for (int i = 0; i < 2; i++) {
            ra[i] = *reinterpret_cast<const float4*>(A + (m0 + lm + i * 64) * lda + kt * 16 + lk);
            rb[i] = *reinterpret_cast<const float4*>(B + (kt * 16 + lbk + i * 8) * ldb + n0 + lbn);
        }
    };
    auto sts = [&](int buf) {
#pragma unroll
        for (int i = 0; i < 2; i++) {
            As[buf][lk + 0][lm + i * 64] = ra[i].x;
            As[buf][lk + 1][lm + i * 64] = ra[i].y;
            As[buf][lk + 2][lm + i * 64] = ra[i].z;
            As[buf][lk + 3][lm + i * 64] = ra[i].w;
            *reinterpret_cast<float4*>(&Bs[buf][lbk + i * 8][lbn]) = rb[i];
        }
    };

    ldg(0); sts(0); __syncthreads();

    for (int kt = 0; kt < ktiles; kt++) {
        const int cur = kt & 1;
        if (kt + 1 < ktiles) ldg(kt + 1);
#pragma unroll
        for (int k = 0; k < 16; k++) {
            float4 a0 = *reinterpret_cast<const float4*>(&As[cur][k][ty * 8]);
            float4 a1 = *reinterpret_cast<const float4*>(&As[cur][k][ty * 8 + 4]);
            float4 b0 = *reinterpret_cast<const float4*>(&Bs[cur][k][tx * 8]);
            float4 b1 = *reinterpret_cast<const float4*>(&Bs[cur][k][tx * 8 + 4]);
            float av[8] = {a0.x, a0.y, a0.z, a0.w, a1.x, a1.y, a1.z, a1.w};
            float bv[8] = {b0.x, b0.y, b0.z, b0.w, b1.x, b1.y, b1.z, b1.w};
#pragma unroll
            for (int i = 0; i < 8; i++)
#pragma unroll
                for (int j = 0; j < 8; j++)
                    acc[i][j] = fmaf(av[i], bv[j], acc[i][j]);
        }
        if (kt + 1 < ktiles) { sts(cur ^ 1); __syncthreads(); }
    }

#pragma unroll
    for (int i = 0; i < 8; i++) {
        const int m = m0 + ty * 8 + i;
        float4 o0, o1;
        o0.x = acc[i][0]; o0.y = acc[i][1]; o0.z = acc[i][2]; o0.w = acc[i][3];
        o1.x = acc[i][4]; o1.y = acc[i][5]; o1.z = acc[i][6]; o1.w = acc[i][7];
        *reinterpret_cast<float4*>(C + m * ldc + n0 + tx * 8)     = o0;
        *reinterpret_cast<float4*>(C + m * ldc + n0 + tx * 8 + 4) = o1;
    }
}

// ============================================================================
// Phase kernels
// ============================================================================

// Q/K/V = x @ W^T + b   (one GEMM per blockIdx.z)
__global__ __launch_bounds__(256, 2)
void qkv_kernel(const float* __restrict__ x,
                const float* __restrict__ wq, const float* __restrict__ bq,
                const float* __restrict__ wk, const float* __restrict__ bk,
                const float* __restrict__ wv, const float* __restrict__ bv)
{
    const float* W; const float* bias; float* Y;
    if      (blockIdx.z == 0) { W = wq; bias = bq; Y = g_Q; }
    else if (blockIdx.z == 1) { W = wk; bias = bk; Y = g_K; }
    else                      { W = wv; bias = bv; Y = g_V; }
    gemm_nt_tile(x, C_, W, C_, Y, C_, bias,
                 blockIdx.y * 128, blockIdx.x * 128, C_ / 16, 1.0f);
}

// S[b,t,s] = K[b,t,:] . Q[b,s,:] / sqrt(C)   -- only tiles with bs <= bt
__global__ __launch_bounds__(256, 2)
void scores_kernel()
{
    const int bs = blockIdx.x, bt = blockIdx.y, b = blockIdx.z;
    if (bs > bt) return;  // fully above causal diagonal
    gemm_nt_tile(g_K + (size_t)b * T_ * C_, C_,
                 g_Q + (size_t)b * T_ * C_, C_,
                 g_S + (size_t)b * T_ * T_, T_, nullptr,
                 bt * 128, bs * 128, C_ / 16, 0.03125f);
}

// Row softmax over s<=t, in place; zero-fill (t, region) so PV tiles read zeros.
__global__ void softmax_kernel()
{
    __shared__ float buf[T_];
    __shared__ float red[256];
    const int row = blockIdx.x;
    const int b = row >> 11;      // / 2048
    const int t = row & (T_ - 1);
    float* S = g_S + (size_t)b * T_ * T_ + (size_t)t * T_;
    const int region = ((t >> 7) + 1) << 7;   // next 128-multiple past t
    const int tid = threadIdx.x;

    float mx = -INFINITY;
    for (int s = tid; s < region; s += 256) {
        float v = (s <= t) ? S[s] : -INFINITY;
        buf[s] = v;
        mx = fmaxf(mx, v);
    }
    red[tid] = mx; __syncthreads();
    for (int off = 128; off; off >>= 1) {
        if (tid < off) red[tid] = fmaxf(red[tid], red[tid + off]);
        __syncthreads();
    }
    mx = red[0];
    __syncthreads();

    float sum = 0.f;
    for (int s = tid; s < region; s += 256) {
        float v = buf[s];
        float e = (v == -INFINITY) ? 0.f : __expf(v - mx);
        buf[s] = e;
        sum += e;
    }
    red[tid] = sum; __syncthreads();
    for (int off = 128; off; off >>= 1) {
        if (tid < off) red[tid] += red[tid + off];
        __syncthreads();
    }
    const float inv = 1.0f / red[0];
    for (int s = tid; s < region; s += 256) S[s] = buf[s] * inv;
}

// O[b,t,c] = sum_{s} P[b,t,s] * V[b,s,c]; k-range truncated to (bt+1)*128
__global__ __launch_bounds__(256, 2)
void pv_kernel(float* __restrict__ out)
{
    const int bc = blockIdx.x, bt = blockIdx.y, b = blockIdx.z;
    gemm_nn_tile(g_S + (size_t)b * T_ * T_, T_,
                 g_V + (size_t)b * T_ * C_, C_,
                 out + (size_t)b * T_ * C_, C_,
                 bt * 128, bc * 128, (bt + 1) * 8);
}

// ============================================================================
extern "C" void kernel_launch(void* const* d_in, const int* in_sizes, int n_in,
                              void* d_out, int out_size)
{
    const float* x  = (const float*)d_in[0];
    const float* wq = (const float*)d_in[1];
    const float* bq = (const float*)d_in[2];
    const float* wk = (const float*)d_in[3];
    const float* bk = (const float*)d_in[4];
    const float* wv = (const float*)d_in[5];
    const float* bv = (const float*)d_in[6];
    float* out = (float*)d_out;

    qkv_kernel   <<<dim3(C_ / 128, MTOT / 128, 3), 256>>>(x, wq, bq, wk, bk, wv, bv);
    scores_kernel<<<dim3(T_ / 128, T_ / 128, B_), 256>>>();
    softmax_kernel<<<MTOT, 256>>>();
    pv_kernel    <<<dim3(C_ / 128, T_ / 128, B_), 256>>>(out);
}